// round 7
// baseline (speedup 1.0000x reference)
#include <cuda_runtime.h>
#include <math.h>
#include <stdint.h>

#define B_  8
#define C_  512
#define DD_ 256
#define HW_ 4096
#define HEADS_ 8
#define CPH_ 32
#define HID_ 16
#define KSPLIT 8

// ---------------- scratch ----------------
__device__ float  g_wt[9*256*512];          // conv weights [tap][co][cin]
__device__ float2 g_twid[4096];
__device__ float  g_xt  [(size_t)B_*C_*HW_];    // x transposed [b][c][n]
__device__ float  g_y   [(size_t)B_*DD_*HW_];
__device__ float  g_fre [(size_t)B_*DD_*HW_];
__device__ float  g_fim [(size_t)B_*DD_*HW_];
__device__ float  g_g1  [(size_t)B_*HID_*HW_];
__device__ float  g_attnS[KSPLIT*64*64*64];
__device__ float2 g_attn2[64*1024];
__device__ float  g_or  [(size_t)B_*DD_*HW_];
__device__ float  g_oi  [(size_t)B_*DD_*HW_];
__device__ float  g_out2[(size_t)B_*C_*HW_];

// ---------------- tf32 helpers ----------------
__device__ __forceinline__ uint32_t f2tf(float f) {
    uint32_t u;
    asm("cvt.rna.tf32.f32 %0, %1;" : "=r"(u) : "f"(f));
    return u;
}
__device__ __forceinline__ void mma8(float c[4], const uint32_t a[4], uint32_t b0, uint32_t b1) {
    asm volatile("mma.sync.aligned.m16n8k8.row.col.f32.tf32.tf32.f32 "
        "{%0,%1,%2,%3}, {%4,%5,%6,%7}, {%8,%9}, {%0,%1,%2,%3};"
        : "+f"(c[0]), "+f"(c[1]), "+f"(c[2]), "+f"(c[3])
        : "r"(a[0]), "r"(a[1]), "r"(a[2]), "r"(a[3]), "r"(b0), "r"(b1));
}

__device__ __forceinline__ int dig4_6(int x) {
    int b = __brev(x) >> 26;
    return ((b & 0x15) << 1) | ((b >> 1) & 0x15);
}
__device__ __forceinline__ int dig4_12(int x) {
    int b = __brev(x) >> 20;
    return ((b & 0x555) << 1) | ((b >> 1) & 0x555);
}

// ---------------- prep ----------------
__global__ void prep_kernel(const float* __restrict__ cw) {
    int tid = blockIdx.x*blockDim.x + threadIdx.x;
    int stride = gridDim.x*blockDim.x;
    if (tid < 4096) {
        float s, c;
        sincosf(-6.28318530717958647692f * (float)tid / 4096.f, &s, &c);
        g_twid[tid] = make_float2(c, s);
    }
    for (int e = tid; e < 9*256*512; e += stride) {
        int tap = e / (256*512);
        int rem = e - tap*256*512;
        int co = rem >> 9;
        int cin = rem & 511;
        g_wt[e] = cw[(co*512 + cin)*9 + tap];
    }
}

// ---------------- x transpose: g_xt[b][c][n] = x[b][n][c] ----------------
__global__ void xt_kernel(const float* __restrict__ x) {
    __shared__ float ts[32][33];
    int b = blockIdx.z;
    int n0 = blockIdx.x*32, c0 = blockIdx.y*32;
    int tx = threadIdx.x & 31, ty = threadIdx.x >> 5;   // 32 x 8
#pragma unroll
    for (int i = 0; i < 4; i++) {
        int n = n0 + ty + i*8;
        ts[ty + i*8][tx] = x[((size_t)b*HW_ + n)*C_ + c0 + tx];
    }
    __syncthreads();
#pragma unroll
    for (int i = 0; i < 4; i++) {
        int c = c0 + ty + i*8;
        g_xt[((size_t)(b*512 + c))*HW_ + n0 + tx] = ts[tx][ty + i*8];
    }
}

// ---------------- conv via tf32 mma, register-staged double buffering ----------
__global__ void conv_mma_kernel(const float* __restrict__ x, const float* __restrict__ cb,
                                const float* __restrict__ bg, const float* __restrict__ bb,
                                const float* __restrict__ bm, const float* __restrict__ bv) {
    __shared__ uint32_t xs[128][36];
    __shared__ uint32_t ws[128][36];
    int b = blockIdx.z, pt = blockIdx.y, ct = blockIdx.x;
    int tid = threadIdx.x, lane = tid & 31, warp = tid >> 5;
    int wm = warp & 3, wn = warp >> 2;
    int g = lane >> 2, t = lane & 3;
    float acc[2][8][4];
#pragma unroll
    for (int i = 0; i < 2; i++)
#pragma unroll
        for (int j = 0; j < 8; j++)
#pragma unroll
            for (int q = 0; q < 4; q++) acc[i][j][q] = 0.f;

    int pos0 = pt*128;
    float4 xbuf[4], wbuf[4];
    // prefetch round 0
    {
        int dh = -3, dw = -3;
        const float* wtp = g_wt + ((size_t)ct*128)*512;
#pragma unroll
        for (int r = 0; r < 4; r++) {
            int e = tid + r*256;
            int pos = e >> 3, ch = e & 7;
            int gp = pos0 + pos;
            int ih = (gp >> 6) + dh, iw = (gp & 63) + dw;
            float4 v = make_float4(0.f, 0.f, 0.f, 0.f);
            if ((unsigned)ih < 64u && (unsigned)iw < 64u)
                v = *(const float4*)&x[((size_t)(b*HW_) + ih*64 + iw)*C_ + ch*4];
            xbuf[r] = v;
            wbuf[r] = *(const float4*)&wtp[(size_t)pos*512 + ch*4];
        }
    }
    for (int rd = 0; rd < 144; rd++) {
        __syncthreads();
#pragma unroll
        for (int r = 0; r < 4; r++) {
            int e = tid + r*256;
            int pos = e >> 3, ch = e & 7;
            *(uint4*)&xs[pos][ch*4] = make_uint4(f2tf(xbuf[r].x), f2tf(xbuf[r].y), f2tf(xbuf[r].z), f2tf(xbuf[r].w));
            *(uint4*)&ws[pos][ch*4] = make_uint4(f2tf(wbuf[r].x), f2tf(wbuf[r].y), f2tf(wbuf[r].z), f2tf(wbuf[r].w));
        }
        __syncthreads();
        if (rd + 1 < 144) {
            int rn = rd + 1;
            int tap = rn >> 4, kc = (rn & 15) << 5;
            int dh = 3*((tap/3) - 1), dw = 3*((tap%3) - 1);
            const float* wtp = g_wt + ((size_t)tap*256 + ct*128)*512;
#pragma unroll
            for (int r = 0; r < 4; r++) {
                int e = tid + r*256;
                int pos = e >> 3, ch = e & 7;
                int gp = pos0 + pos;
                int ih = (gp >> 6) + dh, iw = (gp & 63) + dw;
                float4 v = make_float4(0.f, 0.f, 0.f, 0.f);
                if ((unsigned)ih < 64u && (unsigned)iw < 64u)
                    v = *(const float4*)&x[((size_t)(b*HW_) + ih*64 + iw)*C_ + kc + ch*4];
                xbuf[r] = v;
                wbuf[r] = *(const float4*)&wtp[(size_t)pos*512 + kc + ch*4];
            }
        }
#pragma unroll
        for (int ks = 0; ks < 32; ks += 8) {
            int kr = ks + t;
            uint32_t a[2][4];
#pragma unroll
            for (int mi = 0; mi < 2; mi++) {
                int m0 = wm*32 + mi*16 + g;
                a[mi][0] = ws[m0][kr];
                a[mi][1] = ws[m0+8][kr];
                a[mi][2] = ws[m0][kr+4];
                a[mi][3] = ws[m0+8][kr+4];
            }
#pragma unroll
            for (int ni = 0; ni < 8; ni++) {
                int n0 = wn*64 + ni*8 + g;
                uint32_t b0 = xs[n0][kr];
                uint32_t b1 = xs[n0][kr+4];
                mma8(acc[0][ni], a[0], b0, b1);
                mma8(acc[1][ni], a[1], b0, b1);
            }
        }
    }
#pragma unroll
    for (int mi = 0; mi < 2; mi++) {
#pragma unroll
        for (int half = 0; half < 2; half++) {
            int o = ct*128 + wm*32 + mi*16 + g + half*8;
            float s = bg[o] * rsqrtf(bv[o] + 1e-5f);
            float t0 = cb[o]*s + bb[o] - bm[o]*s;
            float* dst = g_y + ((size_t)(b*DD_ + o))*HW_;
#pragma unroll
            for (int ni = 0; ni < 8; ni++) {
                int pos = pos0 + wn*64 + ni*8 + 2*t;
                float v0 = fmaxf(acc[mi][ni][half*2+0]*s + t0, 0.f);
                float v1 = fmaxf(acc[mi][ni][half*2+1]*s + t0, 0.f);
                *(float2*)&dst[pos] = make_float2(v0, v1);
            }
        }
    }
}

// ---------------- 64x64 2D FFT core, radix-4 ----------------
__device__ __forceinline__ void fft64_2d_r4(float* sr, float* si, int tid, int nt, float sign) {
#pragma unroll
    for (int s = 0; s < 3; s++) {
        int L = 1 << (2*s);
        int stp = 1024 >> (2*s);
        __syncthreads();
        for (int t = tid; t < 1024; t += nt) {
            int row = t >> 4, q = t & 15;
            int j = q & (L-1);
            int grp = q >> (2*s);
            int base = row*65 + grp*(L<<2) + j;
            float2 w1 = g_twid[j*stp];
            float2 w2 = g_twid[2*j*stp];
            float2 w3 = g_twid[3*j*stp];
            float w1i = sign*w1.y, w2i = sign*w2.y, w3i = sign*w3.y;
            float ar = sr[base],       ai = si[base];
            float x1r = sr[base+L],    x1i = si[base+L];
            float x2r = sr[base+2*L],  x2i = si[base+2*L];
            float x3r = sr[base+3*L],  x3i = si[base+3*L];
            float br = x1r*w1.x - x1i*w1i, bi = x1r*w1i + x1i*w1.x;
            float cr = x2r*w2.x - x2i*w2i, ci = x2r*w2i + x2i*w2.x;
            float dr = x3r*w3.x - x3i*w3i, di = x3r*w3i + x3i*w3.x;
            float t0r = ar+cr, t0i = ai+ci;
            float t1r = ar-cr, t1i = ai-ci;
            float t2r = br+dr, t2i = bi+di;
            float t3r = br-dr, t3i = bi-di;
            sr[base]     = t0r+t2r;        si[base]     = t0i+t2i;
            sr[base+2*L] = t0r-t2r;        si[base+2*L] = t0i-t2i;
            sr[base+L]   = t1r + sign*t3i; si[base+L]   = t1i - sign*t3r;
            sr[base+3*L] = t1r - sign*t3i; si[base+3*L] = t1i + sign*t3r;
        }
    }
    __syncthreads();
    for (int e = tid; e < 4096; e += nt) {
        int r = e >> 6, cc = e & 63;
        int d4 = dig4_6(r);
        if (r < d4) {
            float a = sr[r*65+cc]; sr[r*65+cc] = sr[d4*65+cc]; sr[d4*65+cc] = a;
            float b = si[r*65+cc]; si[r*65+cc] = si[d4*65+cc]; si[d4*65+cc] = b;
        }
    }
#pragma unroll
    for (int s = 0; s < 3; s++) {
        int L = 1 << (2*s);
        int stp = 1024 >> (2*s);
        __syncthreads();
        for (int t = tid; t < 1024; t += nt) {
            int col = t & 63, q = t >> 6;
            int j = q & (L-1);
            int grp = q >> (2*s);
            int base = (grp*(L<<2) + j)*65 + col;
            int LL = L*65;
            float2 w1 = g_twid[j*stp];
            float2 w2 = g_twid[2*j*stp];
            float2 w3 = g_twid[3*j*stp];
            float w1i = sign*w1.y, w2i = sign*w2.y, w3i = sign*w3.y;
            float ar = sr[base],       ai = si[base];
            float x1r = sr[base+LL],   x1i = si[base+LL];
            float x2r = sr[base+2*LL], x2i = si[base+2*LL];
            float x3r = sr[base+3*LL], x3i = si[base+3*LL];
            float br = x1r*w1.x - x1i*w1i, bi = x1r*w1i + x1i*w1.x;
            float cr = x2r*w2.x - x2i*w2i, ci = x2r*w2i + x2i*w2.x;
            float dr = x3r*w3.x - x3i*w3i, di = x3r*w3i + x3i*w3.x;
            float t0r = ar+cr, t0i = ai+ci;
            float t1r = ar-cr, t1i = ai-ci;
            float t2r = br+dr, t2i = bi+di;
            float t3r = br-dr, t3i = bi-di;
            sr[base]      = t0r+t2r;        si[base]      = t0i+t2i;
            sr[base+2*LL] = t0r-t2r;        si[base+2*LL] = t0i-t2i;
            sr[base+LL]   = t1r + sign*t3i; si[base+LL]   = t1i - sign*t3r;
            sr[base+3*LL] = t1r - sign*t3i; si[base+3*LL] = t1i + sign*t3r;
        }
    }
    __syncthreads();
}

__global__ void fft2_fwd_kernel() {
    __shared__ float sr[64*65], si[64*65];
    int bc = blockIdx.x;
    int tid = threadIdx.x;
    const float* src = g_y + (size_t)bc*HW_;
    for (int e = tid; e < 4096; e += 512) {
        int r = e >> 6, w = e & 63;
        sr[r*65 + dig4_6(w)] = src[e];
        si[r*65 + dig4_6(w)] = 0.f;
    }
    fft64_2d_r4(sr, si, tid, 512, 1.f);
    float* dr = g_fre + (size_t)bc*HW_;
    float* di = g_fim + (size_t)bc*HW_;
    for (int e = tid; e < 4096; e += 512) {
        dr[e] = sr[(e>>6)*65 + (e&63)];
        di[e] = si[(e>>6)*65 + (e&63)];
    }
}

// ---------------- attention scores ----------------
__global__ void attn_gemm64_kernel() {
    __shared__ uint32_t gs[64][36];
    int bh = blockIdx.x, kq = blockIdx.y;
    int tid = threadIdx.x, lane = tid & 31, warp = tid >> 5;
    int wm = warp & 3, wn = warp >> 2;
    int g = lane >> 2, t = lane & 3;
    float acc[4][4];
#pragma unroll
    for (int i = 0; i < 4; i++)
#pragma unroll
        for (int q = 0; q < 4; q++) acc[i][q] = 0.f;
    const float* fr = g_fre + (size_t)bh*CPH_*HW_;
    const float* fi = g_fim + (size_t)bh*CPH_*HW_;
    int kbeg = kq*(HW_/KSPLIT), kend = kbeg + HW_/KSPLIT;
    for (int k0 = kbeg; k0 < kend; k0 += 32) {
        __syncthreads();
#pragma unroll
        for (int r = 0; r < 2; r++) {
            int e = tid + r*256;
            int row = e >> 3, kqq = e & 7;
            const float* src = (row < 32) ? (fr + (size_t)row*HW_) : (fi + (size_t)(row-32)*HW_);
            float4 v = *(const float4*)&src[k0 + kqq*4];
            uint4 u = make_uint4(f2tf(v.x), f2tf(v.y), f2tf(v.z), f2tf(v.w));
            *(uint4*)&gs[row][kqq*4] = u;
        }
        __syncthreads();
#pragma unroll
        for (int ks = 0; ks < 32; ks += 8) {
            int kr = ks + t;
            uint32_t a[4];
            a[0] = gs[wm*16+g][kr];
            a[1] = gs[wm*16+g+8][kr];
            a[2] = gs[wm*16+g][kr+4];
            a[3] = gs[wm*16+g+8][kr+4];
#pragma unroll
            for (int ni = 0; ni < 4; ni++) {
                int n0 = wn*32 + ni*8 + g;
                mma8(acc[ni], a, gs[n0][kr], gs[n0][kr+4]);
            }
        }
    }
    float* S = g_attnS + ((size_t)(kq*64 + bh))*4096;
#pragma unroll
    for (int ni = 0; ni < 4; ni++) {
        int d = wn*32 + ni*8 + 2*t;
        int c0 = wm*16 + g;
        *(float2*)&S[(size_t)c0*64 + d]     = make_float2(acc[ni][0], acc[ni][1]);
        *(float2*)&S[(size_t)(c0+8)*64 + d] = make_float2(acc[ni][2], acc[ni][3]);
    }
}

// ---------------- attn finalize ----------------
__global__ void attn_fin_kernel(const float* __restrict__ temp) {
    int bh = blockIdx.x;
    int head = bh & 7;
    int tid = threadIdx.x;
    __shared__ float Ss[4096];
    __shared__ float ar_[32*33], ai_[32*33];
    __shared__ float inv[32];
    for (int p = tid; p < 4096; p += 256) {
        float s = 0.f;
#pragma unroll
        for (int q = 0; q < KSPLIT; q++)
            s += g_attnS[((size_t)(q*64 + bh))*4096 + p];
        Ss[p] = s;
    }
    __syncthreads();
    if (tid < 32)
        inv[tid] = rsqrtf(fmaxf(Ss[tid*64 + tid] + Ss[(32+tid)*64 + 32+tid], 1e-24f));
    __syncthreads();
    float tmp = temp[head];
    for (int p = tid; p < 1024; p += 256) {
        int cc = p >> 5, dd = p & 31;
        float sre = Ss[cc*64 + dd] - Ss[(32+cc)*64 + (32+dd)];
        float sim = Ss[cc*64 + (32+dd)] + Ss[(32+cc)*64 + dd];
        float sc = inv[cc] * inv[dd] * tmp;
        ar_[cc*33+dd] = sre*sc;
        ai_[cc*33+dd] = sim*sc;
    }
    __syncthreads();
    int w = tid >> 5, lane = tid & 31;
    for (int r = w; r < 32; r += 8) {
        float vr = ar_[r*33+lane];
        float m = vr;
        for (int o = 16; o; o >>= 1) m = fmaxf(m, __shfl_xor_sync(0xffffffffu, m, o));
        float e = expf(vr - m); float s = e;
        for (int o = 16; o; o >>= 1) s += __shfl_xor_sync(0xffffffffu, s, o);
        ar_[r*33+lane] = e / s;
        float vi = ai_[r*33+lane];
        m = vi;
        for (int o = 16; o; o >>= 1) m = fmaxf(m, __shfl_xor_sync(0xffffffffu, m, o));
        e = expf(vi - m); s = e;
        for (int o = 16; o; o >>= 1) s += __shfl_xor_sync(0xffffffffu, s, o);
        ai_[r*33+lane] = e / s;
    }
    __syncthreads();
    for (int p = tid; p < 1024; p += 256) {
        int k = p >> 5, dd = p & 31;
        float accr = 0.f, acci = 0.f;
#pragma unroll
        for (int cc = 0; cc < 32; cc++) {
            float2 w2 = g_twid[((k*cc) & 31) * 128];
            float wr = w2.x, wi = -w2.y;
            float xr = ar_[cc*33+dd], xi = ai_[cc*33+dd];
            accr += wr*xr - wi*xi;
            acci += wr*xi + wi*xr;
        }
        g_attn2[(size_t)bh*1024 + p] = make_float2(accr*(1.f/32.f), acci*(1.f/32.f));
    }
}

// ---------------- attn apply ----------------
__global__ void attn_apply_kernel() {
    __shared__ float sfr[32][132], sfi[32][132];
    __shared__ float2 a2s[32][32];
    int nc = blockIdx.x, bh = blockIdx.y;
    int tid = threadIdx.x;
    for (int p = tid; p < 1024; p += 256)
        a2s[p>>5][p&31] = g_attn2[(size_t)bh*1024 + p];
    const float* fr = g_fre + (size_t)bh*CPH_*HW_ + nc*128;
    const float* fi = g_fim + (size_t)bh*CPH_*HW_ + nc*128;
    for (int e = tid; e < 1024; e += 256) {
        int d = e >> 5, j = e & 31;
        *(float4*)&sfr[d][j*4] = *(const float4*)&fr[(size_t)d*HW_ + j*4];
        *(float4*)&sfi[d][j*4] = *(const float4*)&fi[(size_t)d*HW_ + j*4];
    }
    __syncthreads();
    int tx = tid & 15, ty = tid >> 4;
    int k0 = ty*2, n0 = tx*8;
    float ar0[8], ai0[8], ar1[8], ai1[8];
#pragma unroll
    for (int j = 0; j < 8; j++) { ar0[j]=0.f; ai0[j]=0.f; ar1[j]=0.f; ai1[j]=0.f; }
#pragma unroll
    for (int d = 0; d < 32; d++) {
        float2 a0 = a2s[k0][d], a1 = a2s[k0+1][d];
        float4 f0 = *(float4*)&sfr[d][n0], f1 = *(float4*)&sfr[d][n0+4];
        float4 h0 = *(float4*)&sfi[d][n0], h1 = *(float4*)&sfi[d][n0+4];
        float frv[8] = {f0.x,f0.y,f0.z,f0.w,f1.x,f1.y,f1.z,f1.w};
        float fiv[8] = {h0.x,h0.y,h0.z,h0.w,h1.x,h1.y,h1.z,h1.w};
#pragma unroll
        for (int j = 0; j < 8; j++) {
            ar0[j] += a0.x*frv[j] - a0.y*fiv[j];
            ai0[j] += a0.x*fiv[j] + a0.y*frv[j];
            ar1[j] += a1.x*frv[j] - a1.y*fiv[j];
            ai1[j] += a1.x*fiv[j] + a1.y*frv[j];
        }
    }
    size_t base0 = ((size_t)(bh*32 + k0))*HW_ + nc*128 + n0;
    size_t base1 = base0 + HW_;
    *(float4*)&g_or[base0]   = make_float4(ar0[0],ar0[1],ar0[2],ar0[3]);
    *(float4*)&g_or[base0+4] = make_float4(ar0[4],ar0[5],ar0[6],ar0[7]);
    *(float4*)&g_oi[base0]   = make_float4(ai0[0],ai0[1],ai0[2],ai0[3]);
    *(float4*)&g_oi[base0+4] = make_float4(ai0[4],ai0[5],ai0[6],ai0[7]);
    *(float4*)&g_or[base1]   = make_float4(ar1[0],ar1[1],ar1[2],ar1[3]);
    *(float4*)&g_or[base1+4] = make_float4(ar1[4],ar1[5],ar1[6],ar1[7]);
    *(float4*)&g_oi[base1]   = make_float4(ai1[0],ai1[1],ai1[2],ai1[3]);
    *(float4*)&g_oi[base1+4] = make_float4(ai1[4],ai1[5],ai1[6],ai1[7]);
}

// ---------------- row ifft4096 radix-4 + abs + residual ----------------
#define SKW(i) ((i) + ((i) >> 7))
__global__ void ifft_row_kernel() {
    __shared__ float sr[4128], si[4128];
    int gid = blockIdx.x;
    int b = gid >> 8, cg = gid & 255;
    int tid = threadIdx.x;
    const float* pr = g_or + (size_t)gid*HW_;
    const float* pi = g_oi + (size_t)gid*HW_;
    for (int nn = tid; nn < 4096; nn += 512) {
        int d = SKW(dig4_12(nn));
        sr[d] = pr[nn];
        si[d] = pi[nn];
    }
#pragma unroll
    for (int s = 0; s < 6; s++) {
        int L = 1 << (2*s);
        int stp = 1024 >> (2*s);
        __syncthreads();
        for (int t = tid; t < 1024; t += 512) {
            int j = t & (L-1);
            int grp = t >> (2*s);
            int base = grp*(L<<2) + j;
            int i0 = SKW(base), i1 = SKW(base+L), i2 = SKW(base+2*L), i3 = SKW(base+3*L);
            float2 w1 = g_twid[j*stp];
            float2 w2 = g_twid[2*j*stp];
            float2 w3 = g_twid[3*j*stp];
            float ar = sr[i0],  ai = si[i0];
            float x1r = sr[i1], x1i = si[i1];
            float x2r = sr[i2], x2i = si[i2];
            float x3r = sr[i3], x3i = si[i3];
            float br = x1r*w1.x + x1i*w1.y, bi = -x1r*w1.y + x1i*w1.x;
            float cr = x2r*w2.x + x2i*w2.y, ci = -x2r*w2.y + x2i*w2.x;
            float dr = x3r*w3.x + x3i*w3.y, di = -x3r*w3.y + x3i*w3.x;
            float t0r = ar+cr, t0i = ai+ci;
            float t1r = ar-cr, t1i = ai-ci;
            float t2r = br+dr, t2i = bi+di;
            float t3r = br-dr, t3i = bi-di;
            sr[i0] = t0r+t2r;  si[i0] = t0i+t2i;
            sr[i2] = t0r-t2r;  si[i2] = t0i-t2i;
            sr[i1] = t1r - t3i; si[i1] = t1i + t3r;
            sr[i3] = t1r + t3i; si[i3] = t1i - t3r;
        }
    }
    __syncthreads();
    const float* xrow = g_xt + ((size_t)(b*512 + cg))*HW_;
    for (int nn = tid; nn < 4096; nn += 512) {
        float re = sr[SKW(nn)], im = si[SKW(nn)];
        float v = sqrtf(re*re + im*im) * (1.f/4096.f) + xrow[nn];
        g_out2[((size_t)(b*512) + cg)*HW_ + nn] = v;
    }
}

// ---------------- gating MLP stage 1 ----------------
__global__ void g1_kernel(const float* __restrict__ w1w, const float* __restrict__ w1b,
                          const float* __restrict__ bg, const float* __restrict__ bb,
                          const float* __restrict__ bm, const float* __restrict__ bv) {
    __shared__ float sw[HID_*DD_];
    __shared__ float sa[HID_], st[HID_];
    int b = blockIdx.y;
    int tid = threadIdx.x;
    int n = blockIdx.x*256 + tid;
    for (int e = tid; e < HID_*DD_; e += 256) sw[e] = w1w[e];
    if (tid < HID_) {
        float s = bg[tid] * rsqrtf(bv[tid] + 1e-5f);
        sa[tid] = s;
        st[tid] = w1b[tid]*s + bb[tid] - bm[tid]*s;
    }
    __syncthreads();
    float acc[HID_];
#pragma unroll
    for (int o = 0; o < HID_; o++) acc[o] = 0.f;
    const float* fr = g_fre + (size_t)b*DD_*HW_ + n;
    for (int c = 0; c < DD_; c++) {
        float v = fr[(size_t)c*HW_];
#pragma unroll
        for (int o = 0; o < HID_; o++) acc[o] += v * sw[o*DD_ + c];
    }
#pragma unroll
    for (int o = 0; o < HID_; o++)
        g_g1[((size_t)(b*HID_ + o))*HW_ + n] = fmaxf(acc[o]*sa[o] + st[o], 0.f);
}

// ---------------- fused gate + ifft2 + abs + residual ----------------
__global__ void ifft2_gate_kernel(const float* __restrict__ w2w,
                                  const float* __restrict__ w2b) {
    __shared__ float sr[64*65], si[64*65];
    __shared__ float w2s[HID_];
    int bc = blockIdx.x;
    int b = bc >> 8, c = bc & 255;
    int tid = threadIdx.x;
    if (tid < HID_) w2s[tid] = w2w[c*HID_ + tid];
    __syncthreads();
    float bias = w2b[c];
    float acc[8];
#pragma unroll
    for (int j = 0; j < 8; j++) acc[j] = bias;
    const float* g1p = g_g1 + (size_t)b*HID_*HW_;
#pragma unroll
    for (int o = 0; o < HID_; o++) {
        float w = w2s[o];
        const float* row = g1p + (size_t)o*HW_;
#pragma unroll
        for (int j = 0; j < 8; j++) acc[j] += w * row[tid + j*512];
    }
    const float* fre = g_fre + (size_t)bc*HW_;
    const float* fim = g_fim + (size_t)bc*HW_;
#pragma unroll
    for (int j = 0; j < 8; j++) {
        int e = tid + j*512;
        float gt = 1.f / (1.f + expf(-acc[j]));
        int r = e >> 6, w = e & 63;
        int dw = dig4_6(w);
        sr[r*65 + dw] = gt * fre[e];
        si[r*65 + dw] = gt * fim[e];
    }
    fft64_2d_r4(sr, si, tid, 512, -1.f);
    const float* xrow = g_xt + ((size_t)(b*512 + 256 + c))*HW_;
    for (int e = tid; e < 4096; e += 512) {
        float re = sr[(e>>6)*65 + (e&63)], im = si[(e>>6)*65 + (e&63)];
        float v = sqrtf(re*re + im*im) * (1.f/4096.f) + xrow[e];
        g_out2[((size_t)(b*512 + 256 + c))*HW_ + e] = v;
    }
}

// ---------------- final projection, register-staged double buffering -------------
__global__ void proj_mma_kernel(const float* __restrict__ pw, const float* __restrict__ pb,
                                float* __restrict__ out) {
    __shared__ uint32_t xs[128][36];
    __shared__ uint32_t ws[128][36];
    int b = blockIdx.z, nt = blockIdx.y, ot = blockIdx.x;
    int tid = threadIdx.x, lane = tid & 31, warp = tid >> 5;
    int wm = warp & 3, wn = warp >> 2;
    int g = lane >> 2, t = lane & 3;
    float acc[2][8][4];
#pragma unroll
    for (int i = 0; i < 2; i++)
#pragma unroll
        for (int j = 0; j < 8; j++)
#pragma unroll
            for (int q = 0; q < 4; q++) acc[i][j][q] = 0.f;

    int n0g = nt*128, o0g = ot*128;
    float4 xbuf[4], wbuf[4];
    {
#pragma unroll
        for (int r = 0; r < 4; r++) {
            int e = tid + r*256;
            int k = e >> 5, n4 = e & 31;
            xbuf[r] = *(const float4*)&g_out2[((size_t)(b*512 + k))*HW_ + n0g + n4*4];
            int o = e >> 3, ch = e & 7;
            wbuf[r] = *(const float4*)&pw[(size_t)(o0g + o)*512 + ch*4];
        }
    }
    for (int rd = 0; rd < 16; rd++) {
        __syncthreads();
#pragma unroll
        for (int r = 0; r < 4; r++) {
            int e = tid + r*256;
            int k = e >> 5, n4 = e & 31;
            xs[n4*4+0][k] = f2tf(xbuf[r].x);
            xs[n4*4+1][k] = f2tf(xbuf[r].y);
            xs[n4*4+2][k] = f2tf(xbuf[r].z);
            xs[n4*4+3][k] = f2tf(xbuf[r].w);
            int o = e >> 3, ch = e & 7;
            *(uint4*)&ws[o][ch*4] = make_uint4(f2tf(wbuf[r].x), f2tf(wbuf[r].y), f2tf(wbuf[r].z), f2tf(wbuf[r].w));
        }
        __syncthreads();
        if (rd + 1 < 16) {
            int kc = (rd + 1) << 5;
#pragma unroll
            for (int r = 0; r < 4; r++) {
                int e = tid + r*256;
                int k = e >> 5, n4 = e & 31;
                xbuf[r] = *(const float4*)&g_out2[((size_t)(b*512 + kc + k))*HW_ + n0g + n4*4];
                int o = e >> 3, ch = e & 7;
                wbuf[r] = *(const float4*)&pw[(size_t)(o0g + o)*512 + kc + ch*4];
            }
        }
#pragma unroll
        for (int ks = 0; ks < 32; ks += 8) {
            int kr = ks + t;
            uint32_t a[2][4];
#pragma unroll
            for (int mi = 0; mi < 2; mi++) {
                int m0 = wm*32 + mi*16 + g;
                a[mi][0] = xs[m0][kr];
                a[mi][1] = xs[m0+8][kr];
                a[mi][2] = xs[m0][kr+4];
                a[mi][3] = xs[m0+8][kr+4];
            }
#pragma unroll
            for (int ni = 0; ni < 8; ni++) {
                int n0 = wn*64 + ni*8 + g;
                uint32_t b0 = ws[n0][kr];
                uint32_t b1 = ws[n0][kr+4];
                mma8(acc[0][ni], a[0], b0, b1);
                mma8(acc[1][ni], a[1], b0, b1);
            }
        }
    }
#pragma unroll
    for (int mi = 0; mi < 2; mi++) {
#pragma unroll
        for (int half = 0; half < 2; half++) {
            int n = n0g + wm*32 + mi*16 + g + half*8;
#pragma unroll
            for (int ni = 0; ni < 8; ni++) {
                int o = o0g + wn*64 + ni*8 + 2*t;
                float2 bias = *(const float2*)&pb[o];
                float v0 = acc[mi][ni][half*2+0] + bias.x;
                float v1 = acc[mi][ni][half*2+1] + bias.y;
                *(float2*)&out[((size_t)b*HW_ + n)*C_ + o] = make_float2(v0, v1);
            }
        }
    }
}

// ---------------- launch ----------------
extern "C" void kernel_launch(void* const* d_in, const int* in_sizes, int n_in,
                              void* d_out, int out_size) {
    const float* x       = (const float*)d_in[0];
    const float* conv2_w = (const float*)d_in[1];
    const float* conv2_b = (const float*)d_in[2];
    const float* bn2_g   = (const float*)d_in[3];
    const float* bn2_b   = (const float*)d_in[4];
    const float* bn2_m   = (const float*)d_in[5];
    const float* bn2_v   = (const float*)d_in[6];
    const float* temp    = (const float*)d_in[7];
    const float* w1_w    = (const float*)d_in[8];
    const float* w1_b    = (const float*)d_in[9];
    const float* bnw_g   = (const float*)d_in[10];
    const float* bnw_b   = (const float*)d_in[11];
    const float* bnw_m   = (const float*)d_in[12];
    const float* bnw_v   = (const float*)d_in[13];
    const float* w2_w    = (const float*)d_in[14];
    const float* w2_b    = (const float*)d_in[15];
    const float* proj_w  = (const float*)d_in[16];
    const float* proj_b  = (const float*)d_in[17];
    float* out = (float*)d_out;

    prep_kernel<<<1024, 256>>>(conv2_w);
    xt_kernel<<<dim3(128, 16, 8), 256>>>(x);
    conv_mma_kernel<<<dim3(2, 32, 8), 256>>>(x, conv2_b, bn2_g, bn2_b, bn2_m, bn2_v);
    fft2_fwd_kernel<<<2048, 512>>>();
    attn_gemm64_kernel<<<dim3(64, KSPLIT), 256>>>();
    attn_fin_kernel<<<64, 256>>>(temp);
    attn_apply_kernel<<<dim3(32, 64), 256>>>();
    ifft_row_kernel<<<2048, 512>>>();
    g1_kernel<<<dim3(16, 8), 256>>>(w1_w, w1_b, bnw_g, bnw_b, bnw_m, bnw_v);
    ifft2_gate_kernel<<<2048, 512>>>(w2_w, w2_b);
    proj_mma_kernel<<<dim3(4, 32, 8), 256>>>(proj_w, proj_b, out);
}